// round 10
// baseline (speedup 1.0000x reference)
#include <cuda_runtime.h>
#include <cuda_bf16.h>
#include <cstdint>

#define B_SZ   8
#define S_LEN  2048
#define E_DIM  768
#define H_DIM  128
#define M_TOTAL (B_SZ * S_LEN)

// hi/lo bf16 split inputs (produced by split kernels)
__device__ __nv_bfloat16 g_xh[M_TOTAL * E_DIM];
__device__ __nv_bfloat16 g_xl[M_TOTAL * E_DIM];
__device__ __nv_bfloat16 g_wh[3 * H_DIM * E_DIM];
__device__ __nv_bfloat16 g_wl[3 * H_DIM * E_DIM];
// hi/lo bf16 split q, k, v (q pre-scaled by 1/sqrt(128)), row-major
__device__ __nv_bfloat16 g_qh[M_TOTAL * H_DIM];
__device__ __nv_bfloat16 g_ql[M_TOTAL * H_DIM];
__device__ __nv_bfloat16 g_kh[M_TOTAL * H_DIM];
__device__ __nv_bfloat16 g_kl[M_TOTAL * H_DIM];
__device__ __nv_bfloat16 g_vh[M_TOTAL * H_DIM];
__device__ __nv_bfloat16 g_vl[M_TOTAL * H_DIM];

// ---------------------------------------------------------------------------
// helpers (baseline PTX only: mma.sync + ldmatrix + cp.async)
// ---------------------------------------------------------------------------
__device__ __forceinline__ uint32_t smem_u32(const void* p) {
    uint32_t a;
    asm("{ .reg .u64 t; cvta.to.shared.u64 t, %1; cvt.u32.u64 %0, t; }"
        : "=r"(a) : "l"(p));
    return a;
}
__device__ __forceinline__ void mma16816(float c[4],
                                         uint32_t a0, uint32_t a1, uint32_t a2, uint32_t a3,
                                         uint32_t b0, uint32_t b1) {
    asm volatile(
        "mma.sync.aligned.m16n8k16.row.col.f32.bf16.bf16.f32 "
        "{%0,%1,%2,%3}, {%4,%5,%6,%7}, {%8,%9}, {%0,%1,%2,%3};"
        : "+f"(c[0]), "+f"(c[1]), "+f"(c[2]), "+f"(c[3])
        : "r"(a0), "r"(a1), "r"(a2), "r"(a3), "r"(b0), "r"(b1));
}
__device__ __forceinline__ void ldmx4(uint32_t r[4], uint32_t addr) {
    asm volatile("ldmatrix.sync.aligned.m8n8.x4.shared.b16 {%0,%1,%2,%3}, [%4];"
                 : "=r"(r[0]), "=r"(r[1]), "=r"(r[2]), "=r"(r[3]) : "r"(addr));
}
__device__ __forceinline__ void ldmx4t(uint32_t r[4], uint32_t addr) {
    asm volatile("ldmatrix.sync.aligned.m8n8.x4.trans.shared.b16 {%0,%1,%2,%3}, [%4];"
                 : "=r"(r[0]), "=r"(r[1]), "=r"(r[2]), "=r"(r[3]) : "r"(addr));
}
__device__ __forceinline__ void cp16(uint32_t s, const void* g) {
    asm volatile("cp.async.cg.shared.global [%0], [%1], 16;" :: "r"(s), "l"(g));
}
#define CP_COMMIT()  asm volatile("cp.async.commit_group;" ::: "memory")
#define CP_WAIT1()   asm volatile("cp.async.wait_group 1;" ::: "memory")
#define CP_WAIT0()   asm volatile("cp.async.wait_group 0;" ::: "memory")

// hi/lo bf16 split of two floats packed bf16x2 (first value in low half)
__device__ __forceinline__ void split2(float a, float b, uint32_t& hi, uint32_t& lo) {
    __nv_bfloat16 ah = __float2bfloat16(a);
    __nv_bfloat16 bh = __float2bfloat16(b);
    __nv_bfloat16 al = __float2bfloat16(a - __bfloat162float(ah));
    __nv_bfloat16 bl = __float2bfloat16(b - __bfloat162float(bh));
    hi = ((uint32_t)__bfloat16_as_ushort(bh) << 16) | (uint32_t)__bfloat16_as_ushort(ah);
    lo = ((uint32_t)__bfloat16_as_ushort(bl) << 16) | (uint32_t)__bfloat16_as_ushort(al);
}

// ---------------------------------------------------------------------------
// Kernel 0a/0b: one-time hi/lo splits (memory-bound)
// ---------------------------------------------------------------------------
__global__ __launch_bounds__(256)
void split_x_kernel(const float* __restrict__ X, const float* __restrict__ mask)
{
    int idx = (blockIdx.x * 256 + threadIdx.x) * 4;
    float mk = mask[idx / E_DIM];
    float4 v = *(const float4*)&X[idx];
    uint32_t h0, l0, h1, l1;
    split2(v.x * mk, v.y * mk, h0, l0);
    split2(v.z * mk, v.w * mk, h1, l1);
    *(uint2*)&g_xh[idx] = make_uint2(h0, h1);
    *(uint2*)&g_xl[idx] = make_uint2(l0, l1);
}
__global__ __launch_bounds__(256)
void split_w_kernel(const float* __restrict__ Wq, const float* __restrict__ Wk,
                    const float* __restrict__ Wv)
{
    int idx = (blockIdx.x * 256 + threadIdx.x) * 4;
    int o = idx / (H_DIM * E_DIM);
    int r = idx - o * (H_DIM * E_DIM);
    const float* W = (o == 0) ? Wq : (o == 1 ? Wk : Wv);
    float4 v = *(const float4*)&W[r];
    uint32_t h0, l0, h1, l1;
    split2(v.x, v.y, h0, l0);
    split2(v.z, v.w, h1, l1);
    *(uint2*)&g_wh[idx] = make_uint2(h0, h1);
    *(uint2*)&g_wl[idx] = make_uint2(l0, l1);
}

// ---------------------------------------------------------------------------
// Kernel 1: QKV projection, bf16x3 warp MMA, cp.async double-buffered.
// grid=(256,3), block=128.  BM=64, BN=128, BK=64.
// Stage (bf16 elems, stride 72): Xh 0, Xl 4608, Wh 9216, Wl 18432.
// W b-fragments via ldmatrix.x4 (2 j-values per instruction).
// ---------------------------------------------------------------------------
#define QAST 72
#define QSTG 27648
#define QKV_SMEM (2 * 55296)

__global__ __launch_bounds__(128)
void qkv_mma_kernel()
{
    extern __shared__ __align__(16) __nv_bfloat16 sm_q[];
    const int tid  = threadIdx.x;
    const int lane = tid & 31;
    const int wid  = tid >> 5;
    const int m0   = blockIdx.x * 64;
    const int o    = blockIdx.y;
    const size_t wbase = (size_t)o * H_DIM * E_DIM;

    float c[16][4];
#pragma unroll
    for (int j = 0; j < 16; j++)
#pragma unroll
        for (int i = 0; i < 4; i++) c[j][i] = 0.f;

    auto issue = [&](int cc, int s) {
        uint32_t sb = smem_u32(sm_q + s * QSTG);
        const int k0 = cc * 64;
#pragma unroll
        for (int i = 0; i < 4; i++) {
            int idx = tid + i * 128;
            int row = idx >> 3, c16 = idx & 7;
            size_t g = (size_t)(m0 + row) * E_DIM + k0 + c16 * 8;
            uint32_t d = sb + (row * QAST + c16 * 8) * 2;
            cp16(d,        &g_xh[g]);
            cp16(d + 9216, &g_xl[g]);
        }
#pragma unroll
        for (int i = 0; i < 8; i++) {
            int idx = tid + i * 128;
            int row = idx >> 3, c16 = idx & 7;
            size_t g = wbase + (size_t)row * E_DIM + k0 + c16 * 8;
            uint32_t d = sb + (9216 + row * QAST + c16 * 8) * 2;
            cp16(d,         &g_wh[g]);
            cp16(d + 18432, &g_wl[g]);
        }
    };

    issue(0, 0); CP_COMMIT();

    // b-frag ldmatrix lane mapping (row within 16-row jp block, k-half)
    const int brow = ((lane >> 4) & 1) * 8 + (lane & 7);
    const int bcol = ((lane >> 3) & 1) * 8;

    for (int cc = 0; cc < 12; cc++) {
        if (cc < 11) { issue(cc + 1, (cc + 1) & 1); CP_COMMIT(); CP_WAIT1(); }
        else CP_WAIT0();
        __syncthreads();

        const uint32_t xh_base = smem_u32(sm_q + (cc & 1) * QSTG);
        const uint32_t wh_base = xh_base + 18432;   // Wh bytes
#pragma unroll
        for (int kd = 0; kd < 4; kd++) {
            uint32_t ah[4], al[4];
            uint32_t aaddr = xh_base +
                ((wid * 16 + (lane & 15)) * QAST + kd * 16 + ((lane >> 4) << 3)) * 2;
            ldmx4(ah, aaddr);
            ldmx4(al, aaddr + 9216);
#pragma unroll
            for (int jp = 0; jp < 8; jp++) {
                uint32_t bh[4], bl[4];
                uint32_t baddr = wh_base +
                    ((jp * 16 + brow) * QAST + kd * 16 + bcol) * 2;
                ldmx4(bh, baddr);
                ldmx4(bl, baddr + 18432);
                mma16816(c[2 * jp],     ah[0], ah[1], ah[2], ah[3], bh[0], bh[1]);
                mma16816(c[2 * jp],     ah[0], ah[1], ah[2], ah[3], bl[0], bl[1]);
                mma16816(c[2 * jp],     al[0], al[1], al[2], al[3], bh[0], bh[1]);
                mma16816(c[2 * jp + 1], ah[0], ah[1], ah[2], ah[3], bh[2], bh[3]);
                mma16816(c[2 * jp + 1], ah[0], ah[1], ah[2], ah[3], bl[2], bl[3]);
                mma16816(c[2 * jp + 1], al[0], al[1], al[2], al[3], bh[2], bh[3]);
            }
        }
        __syncthreads();
    }

    // --- epilogue: split accumulators to hi/lo bf16 ---
    const float sc = (o == 0) ? 0.0883883476483184f : 1.f;   // 1/sqrt(128) on q
    __nv_bfloat16* oh = (o == 0) ? g_qh : (o == 1 ? g_kh : g_vh);
    __nv_bfloat16* ol = (o == 0) ? g_ql : (o == 1 ? g_kl : g_vl);
    const size_t r0 = (size_t)(m0 + wid * 16 + (lane >> 2)) * H_DIM;
    const size_t r1 = r0 + 8 * H_DIM;
#pragma unroll
    for (int j = 0; j < 16; j++) {
        int col = j * 8 + (lane & 3) * 2;
        uint32_t h, l;
        split2(c[j][0] * sc, c[j][1] * sc, h, l);
        *(uint32_t*)&oh[r0 + col] = h;
        *(uint32_t*)&ol[r0 + col] = l;
        split2(c[j][2] * sc, c[j][3] * sc, h, l);
        *(uint32_t*)&oh[r1 + col] = h;
        *(uint32_t*)&ol[r1 + col] = l;
    }
}

// ---------------------------------------------------------------------------
// Kernel 2: causal flash attention, bf16x3 warp MMA.  QT=64, KT=32.
// grid=(32,8) long-first, block=128.  104448 B smem -> 2 CTAs/SM.
// Smem (bf16 elems): Qh 0, Ql 8704 (stride 136, 64 rows);
// KV stage s @ 17408+s*17408: Kh +0, Kl +4352, Vh +8704, Vl +13056 (32 rows).
// K b-frags via ldmx4 (2 j per instr); V b-frags via ldmx4t (2 dn per instr).
// ---------------------------------------------------------------------------
#define AST 136
#define KVSTG 17408
#define ATT_SMEM 104448

__global__ __launch_bounds__(128, 2)
void attn_mma_kernel(float* __restrict__ out)
{
    extern __shared__ __align__(16) __nv_bfloat16 sm_a[];

    const int tid  = threadIdx.x;
    const int lane = tid & 31;
    const int wid  = tid >> 5;
    const int b    = blockIdx.y;
    const int qt   = 31 - (int)blockIdx.x;     // long blocks first
    const int q0   = qt * 64;
    const int nsteps = 2 * qt + 2;

    const uint32_t qh_base = smem_u32(sm_a);

    auto issue_kv = [&](int kts, int s) {
        uint32_t kb = smem_u32(sm_a + 17408 + s * KVSTG);
#pragma unroll
        for (int i = 0; i < 4; i++) {
            int idx = tid + i * 128;           // 0..511: 32 rows x 16 chunks
            int row = idx >> 4, c8 = idx & 15;
            size_t g = ((size_t)b * S_LEN + kts * 32 + row) * H_DIM + c8 * 8;
            uint32_t d = kb + (row * AST + c8 * 8) * 2;
            cp16(d,         &g_kh[g]);
            cp16(d + 8704,  &g_kl[g]);
            cp16(d + 17408, &g_vh[g]);
            cp16(d + 26112, &g_vl[g]);
        }
    };

    issue_kv(0, 0); CP_COMMIT();

    // --- stage Q (hi/lo), persists across kv steps ---
#pragma unroll
    for (int i = 0; i < 8; i++) {
        int idx = tid + i * 128;
        int row = idx >> 4, c8 = idx & 15;
        size_t g = ((size_t)b * S_LEN + q0 + row) * H_DIM + c8 * 8;
        *(uint4*)&sm_a[row * AST + c8 * 8]        = *(const uint4*)&g_qh[g];
        *(uint4*)&sm_a[8704 + row * AST + c8 * 8] = *(const uint4*)&g_ql[g];
    }

    float o_[16][4];
#pragma unroll
    for (int d = 0; d < 16; d++)
#pragma unroll
        for (int i = 0; i < 4; i++) o_[d][i] = 0.f;
    float lsum0 = 0.f, lsum1 = 0.f;

    const int colb = (lane & 3) * 2;
    const int r0l  = wid * 16 + (lane >> 2);
    const int r1l  = r0l + 8;
    // non-trans b-frag lane map (K); trans b-frag lane map (V)
    const int kbrow = ((lane >> 4) & 1) * 8 + (lane & 7);
    const int kbcol = ((lane >> 3) & 1) * 8;
    const int vbrow = ((lane >> 3) & 1) * 8 + (lane & 7);
    const int vbcol = ((lane >> 4) & 1) * 8;

    for (int kts = 0; kts < nsteps; kts++) {
        if (kts + 1 < nsteps) { issue_kv(kts + 1, (kts + 1) & 1); CP_COMMIT(); CP_WAIT1(); }
        else CP_WAIT0();
        __syncthreads();

        const uint32_t kb = smem_u32(sm_a + 17408 + (kts & 1) * KVSTG);
        const uint32_t vb = kb + 17408;        // Vh bytes

        // --- S = Q K^T  (64q x 32k) ---
        float s[4][4];
#pragma unroll
        for (int j = 0; j < 4; j++)
#pragma unroll
            for (int i = 0; i < 4; i++) s[j][i] = 0.f;

#pragma unroll
        for (int kd = 0; kd < 8; kd++) {
            uint32_t ah[4], al[4];
            uint32_t aaddr = qh_base +
                ((wid * 16 + (lane & 15)) * AST + kd * 16 + ((lane >> 4) << 3)) * 2;
            ldmx4(ah, aaddr);
            ldmx4(al, aaddr + 17408);
#pragma unroll
            for (int jp = 0; jp < 2; jp++) {
                uint32_t bh[4], bl[4];
                uint32_t baddr = kb + ((jp * 16 + kbrow) * AST + kd * 16 + kbcol) * 2;
                ldmx4(bh, baddr);
                ldmx4(bl, baddr + 8704);
                mma16816(s[2 * jp],     ah[0], ah[1], ah[2], ah[3], bh[0], bh[1]);
                mma16816(s[2 * jp],     ah[0], ah[1], ah[2], ah[3], bl[0], bl[1]);
                mma16816(s[2 * jp],     al[0], al[1], al[2], al[3], bh[0], bh[1]);
                mma16816(s[2 * jp + 1], ah[0], ah[1], ah[2], ah[3], bh[2], bh[3]);
                mma16816(s[2 * jp + 1], ah[0], ah[1], ah[2], ah[3], bl[2], bl[3]);
                mma16816(s[2 * jp + 1], al[0], al[1], al[2], al[3], bh[2], bh[3]);
            }
        }

        // --- exp (+ causal mask), row sums ---
        const bool diag = (kts >= 2 * qt);
        const int dof = kts * 32 - q0;
        float rs0 = 0.f, rs1 = 0.f;
#pragma unroll
        for (int j = 0; j < 4; j++) {
            float e0 = __expf(s[j][0]);
            float e1 = __expf(s[j][1]);
            float e2 = __expf(s[j][2]);
            float e3 = __expf(s[j][3]);
            if (diag) {
                int cc = j * 8 + colb + dof;
                if (cc     > r0l) e0 = 0.f;
                if (cc + 1 > r0l) e1 = 0.f;
                if (cc     > r1l) e2 = 0.f;
                if (cc + 1 > r1l) e3 = 0.f;
            }
            s[j][0] = e0; s[j][1] = e1; s[j][2] = e2; s[j][3] = e3;
            rs0 += e0 + e1;
            rs1 += e2 + e3;
        }
        rs0 += __shfl_xor_sync(0xffffffffu, rs0, 1);
        rs0 += __shfl_xor_sync(0xffffffffu, rs0, 2);
        rs1 += __shfl_xor_sync(0xffffffffu, rs1, 1);
        rs1 += __shfl_xor_sync(0xffffffffu, rs1, 2);
        lsum0 += rs0;
        lsum1 += rs1;

        // --- O += P V.  P A-frags in-register from S C-frags. ---
#pragma unroll
        for (int j2 = 0; j2 < 2; j2++) {
            uint32_t ph[4], pl[4];
            split2(s[2 * j2][0],     s[2 * j2][1],     ph[0], pl[0]);
            split2(s[2 * j2][2],     s[2 * j2][3],     ph[1], pl[1]);
            split2(s[2 * j2 + 1][0], s[2 * j2 + 1][1], ph[2], pl[2]);
            split2(s[2 * j2 + 1][2], s[2 * j2 + 1][3], ph[3], pl[3]);
#pragma unroll
            for (int d2 = 0; d2 < 8; d2++) {
                uint32_t vh[4], vl[4];
                uint32_t vaddr = vb + ((j2 * 16 + vbrow) * AST + d2 * 16 + vbcol) * 2;
                ldmx4t(vh, vaddr);
                ldmx4t(vl, vaddr + 8704);
                mma16816(o_[2 * d2],     ph[0], ph[1], ph[2], ph[3], vh[0], vh[1]);
                mma16816(o_[2 * d2],     ph[0], ph[1], ph[2], ph[3], vl[0], vl[1]);
                mma16816(o_[2 * d2],     pl[0], pl[1], pl[2], pl[3], vh[0], vh[1]);
                mma16816(o_[2 * d2 + 1], ph[0], ph[1], ph[2], ph[3], vh[2], vh[3]);
                mma16816(o_[2 * d2 + 1], ph[0], ph[1], ph[2], ph[3], vl[2], vl[3]);
                mma16816(o_[2 * d2 + 1], pl[0], pl[1], pl[2], pl[3], vh[2], vh[3]);
            }
        }
        __syncthreads();
    }

    // --- epilogue ---
    const float inv0 = 1.f / lsum0;
    const float inv1 = 1.f / lsum1;
    const size_t gr0 = ((size_t)b * S_LEN + q0 + r0l) * H_DIM;
    const size_t gr1 = gr0 + 8 * H_DIM;
#pragma unroll
    for (int dn = 0; dn < 16; dn++) {
        int col = dn * 8 + colb;
        *(float2*)&out[gr0 + col] = make_float2(o_[dn][0] * inv0, o_[dn][1] * inv0);
        *(float2*)&out[gr1 + col] = make_float2(o_[dn][2] * inv1, o_[dn][3] * inv1);
    }
}

// ---------------------------------------------------------------------------
extern "C" void kernel_launch(void* const* d_in, const int* in_sizes, int n_in,
                              void* d_out, int out_size)
{
    const float* X    = (const float*)d_in[0];
    const float* mask = (const float*)d_in[1];
    const float* Wq   = (const float*)d_in[2];
    const float* Wk   = (const float*)d_in[3];
    const float* Wv   = (const float*)d_in[4];
    float* out        = (float*)d_out;

    split_x_kernel<<<M_TOTAL * E_DIM / 4 / 256, 256>>>(X, mask);
    split_w_kernel<<<3 * H_DIM * E_DIM / 4 / 256, 256>>>(Wq, Wk, Wv);

    cudaFuncSetAttribute(qkv_mma_kernel,
                         cudaFuncAttributeMaxDynamicSharedMemorySize, QKV_SMEM);
    dim3 g1(M_TOTAL / 64, 3);
    qkv_mma_kernel<<<g1, 128, QKV_SMEM>>>();

    cudaFuncSetAttribute(attn_mma_kernel,
                         cudaFuncAttributeMaxDynamicSharedMemorySize, ATT_SMEM);
    dim3 g2(32, B_SZ);
    attn_mma_kernel<<<g2, 128, ATT_SMEM>>>(out);
}

// round 11
// speedup vs baseline: 1.1488x; 1.1488x over previous
#include <cuda_runtime.h>
#include <cuda_bf16.h>
#include <cstdint>

#define B_SZ   8
#define S_LEN  2048
#define E_DIM  768
#define H_DIM  128
#define M_TOTAL (B_SZ * S_LEN)

// hi/lo bf16 split inputs (produced by split kernels)
__device__ __nv_bfloat16 g_xh[M_TOTAL * E_DIM];
__device__ __nv_bfloat16 g_xl[M_TOTAL * E_DIM];
__device__ __nv_bfloat16 g_wh[3 * H_DIM * E_DIM];
__device__ __nv_bfloat16 g_wl[3 * H_DIM * E_DIM];
// hi/lo bf16 split q, k, v (q pre-scaled by 1/sqrt(128)), row-major
__device__ __nv_bfloat16 g_qh[M_TOTAL * H_DIM];
__device__ __nv_bfloat16 g_ql[M_TOTAL * H_DIM];
__device__ __nv_bfloat16 g_kh[M_TOTAL * H_DIM];
__device__ __nv_bfloat16 g_kl[M_TOTAL * H_DIM];
__device__ __nv_bfloat16 g_vh[M_TOTAL * H_DIM];
__device__ __nv_bfloat16 g_vl[M_TOTAL * H_DIM];
// split-KV partials (qt >= 8 rows only: rows 1024..2047 of each batch)
__device__ float g_po[2 * 8 * 1024 * 128];
__device__ float g_pl[2 * 8 * 1024];

// ---------------------------------------------------------------------------
// helpers (baseline PTX only: mma.sync + ldmatrix + cp.async)
// ---------------------------------------------------------------------------
__device__ __forceinline__ uint32_t smem_u32(const void* p) {
    uint32_t a;
    asm("{ .reg .u64 t; cvta.to.shared.u64 t, %1; cvt.u32.u64 %0, t; }"
        : "=r"(a) : "l"(p));
    return a;
}
__device__ __forceinline__ void mma16816(float c[4],
                                         uint32_t a0, uint32_t a1, uint32_t a2, uint32_t a3,
                                         uint32_t b0, uint32_t b1) {
    asm volatile(
        "mma.sync.aligned.m16n8k16.row.col.f32.bf16.bf16.f32 "
        "{%0,%1,%2,%3}, {%4,%5,%6,%7}, {%8,%9}, {%0,%1,%2,%3};"
        : "+f"(c[0]), "+f"(c[1]), "+f"(c[2]), "+f"(c[3])
        : "r"(a0), "r"(a1), "r"(a2), "r"(a3), "r"(b0), "r"(b1));
}
__device__ __forceinline__ void ldmx4(uint32_t r[4], uint32_t addr) {
    asm volatile("ldmatrix.sync.aligned.m8n8.x4.shared.b16 {%0,%1,%2,%3}, [%4];"
                 : "=r"(r[0]), "=r"(r[1]), "=r"(r[2]), "=r"(r[3]) : "r"(addr));
}
__device__ __forceinline__ void ldmx4t(uint32_t r[4], uint32_t addr) {
    asm volatile("ldmatrix.sync.aligned.m8n8.x4.trans.shared.b16 {%0,%1,%2,%3}, [%4];"
                 : "=r"(r[0]), "=r"(r[1]), "=r"(r[2]), "=r"(r[3]) : "r"(addr));
}
__device__ __forceinline__ void cp16(uint32_t s, const void* g) {
    asm volatile("cp.async.cg.shared.global [%0], [%1], 16;" :: "r"(s), "l"(g));
}
#define CP_COMMIT()  asm volatile("cp.async.commit_group;" ::: "memory")
#define CP_WAIT1()   asm volatile("cp.async.wait_group 1;" ::: "memory")
#define CP_WAIT0()   asm volatile("cp.async.wait_group 0;" ::: "memory")

// hi/lo bf16 split of two floats packed bf16x2 (first value in low half)
__device__ __forceinline__ void split2(float a, float b, uint32_t& hi, uint32_t& lo) {
    __nv_bfloat16 ah = __float2bfloat16(a);
    __nv_bfloat16 bh = __float2bfloat16(b);
    __nv_bfloat16 al = __float2bfloat16(a - __bfloat162float(ah));
    __nv_bfloat16 bl = __float2bfloat16(b - __bfloat162float(bh));
    hi = ((uint32_t)__bfloat16_as_ushort(bh) << 16) | (uint32_t)__bfloat16_as_ushort(ah);
    lo = ((uint32_t)__bfloat16_as_ushort(bl) << 16) | (uint32_t)__bfloat16_as_ushort(al);
}

// ---------------------------------------------------------------------------
// Kernel 0a/0b: one-time hi/lo splits (memory-bound)
// ---------------------------------------------------------------------------
__global__ __launch_bounds__(256)
void split_x_kernel(const float* __restrict__ X, const float* __restrict__ mask)
{
    int idx = (blockIdx.x * 256 + threadIdx.x) * 4;
    float mk = mask[idx / E_DIM];
    float4 v = *(const float4*)&X[idx];
    uint32_t h0, l0, h1, l1;
    split2(v.x * mk, v.y * mk, h0, l0);
    split2(v.z * mk, v.w * mk, h1, l1);
    *(uint2*)&g_xh[idx] = make_uint2(h0, h1);
    *(uint2*)&g_xl[idx] = make_uint2(l0, l1);
}
__global__ __launch_bounds__(256)
void split_w_kernel(const float* __restrict__ Wq, const float* __restrict__ Wk,
                    const float* __restrict__ Wv)
{
    int idx = (blockIdx.x * 256 + threadIdx.x) * 4;
    int o = idx / (H_DIM * E_DIM);
    int r = idx - o * (H_DIM * E_DIM);
    const float* W = (o == 0) ? Wq : (o == 1 ? Wk : Wv);
    float4 v = *(const float4*)&W[r];
    uint32_t h0, l0, h1, l1;
    split2(v.x, v.y, h0, l0);
    split2(v.z, v.w, h1, l1);
    *(uint2*)&g_wh[idx] = make_uint2(h0, h1);
    *(uint2*)&g_wl[idx] = make_uint2(l0, l1);
}

// ---------------------------------------------------------------------------
// Kernel 1: QKV projection, bf16x3 warp MMA, cp.async double-buffered.
// grid=(256,3), block=128.  BM=64, BN=128, BK=64.  (validated in R9/R10)
// ---------------------------------------------------------------------------
#define QAST 72
#define QSTG 27648
#define QKV_SMEM (2 * 55296)

__global__ __launch_bounds__(128)
void qkv_mma_kernel()
{
    extern __shared__ __align__(16) __nv_bfloat16 sm_q[];
    const int tid  = threadIdx.x;
    const int lane = tid & 31;
    const int wid  = tid >> 5;
    const int m0   = blockIdx.x * 64;
    const int o    = blockIdx.y;
    const size_t wbase = (size_t)o * H_DIM * E_DIM;

    float c[16][4];
#pragma unroll
    for (int j = 0; j < 16; j++)
#pragma unroll
        for (int i = 0; i < 4; i++) c[j][i] = 0.f;

    auto issue = [&](int cc, int s) {
        uint32_t sb = smem_u32(sm_q + s * QSTG);
        const int k0 = cc * 64;
#pragma unroll
        for (int i = 0; i < 4; i++) {
            int idx = tid + i * 128;
            int row = idx >> 3, c16 = idx & 7;
            size_t g = (size_t)(m0 + row) * E_DIM + k0 + c16 * 8;
            uint32_t d = sb + (row * QAST + c16 * 8) * 2;
            cp16(d,        &g_xh[g]);
            cp16(d + 9216, &g_xl[g]);
        }
#pragma unroll
        for (int i = 0; i < 8; i++) {
            int idx = tid + i * 128;
            int row = idx >> 3, c16 = idx & 7;
            size_t g = wbase + (size_t)row * E_DIM + k0 + c16 * 8;
            uint32_t d = sb + (9216 + row * QAST + c16 * 8) * 2;
            cp16(d,         &g_wh[g]);
            cp16(d + 18432, &g_wl[g]);
        }
    };

    issue(0, 0); CP_COMMIT();

    const int brow = ((lane >> 4) & 1) * 8 + (lane & 7);
    const int bcol = ((lane >> 3) & 1) * 8;

    for (int cc = 0; cc < 12; cc++) {
        if (cc < 11) { issue(cc + 1, (cc + 1) & 1); CP_COMMIT(); CP_WAIT1(); }
        else CP_WAIT0();
        __syncthreads();

        const uint32_t xh_base = smem_u32(sm_q + (cc & 1) * QSTG);
        const uint32_t wh_base = xh_base + 18432;
#pragma unroll
        for (int kd = 0; kd < 4; kd++) {
            uint32_t ah[4], al[4];
            uint32_t aaddr = xh_base +
                ((wid * 16 + (lane & 15)) * QAST + kd * 16 + ((lane >> 4) << 3)) * 2;
            ldmx4(ah, aaddr);
            ldmx4(al, aaddr + 9216);
#pragma unroll
            for (int jp = 0; jp < 8; jp++) {
                uint32_t bh[4], bl[4];
                uint32_t baddr = wh_base +
                    ((jp * 16 + brow) * QAST + kd * 16 + bcol) * 2;
                ldmx4(bh, baddr);
                ldmx4(bl, baddr + 18432);
                mma16816(c[2 * jp],     ah[0], ah[1], ah[2], ah[3], bh[0], bh[1]);
                mma16816(c[2 * jp],     ah[0], ah[1], ah[2], ah[3], bl[0], bl[1]);
                mma16816(c[2 * jp],     al[0], al[1], al[2], al[3], bh[0], bh[1]);
                mma16816(c[2 * jp + 1], ah[0], ah[1], ah[2], ah[3], bh[2], bh[3]);
                mma16816(c[2 * jp + 1], ah[0], ah[1], ah[2], ah[3], bl[2], bl[3]);
                mma16816(c[2 * jp + 1], al[0], al[1], al[2], al[3], bh[2], bh[3]);
            }
        }
        __syncthreads();
    }

    const float sc = (o == 0) ? 0.0883883476483184f : 1.f;
    __nv_bfloat16* oh = (o == 0) ? g_qh : (o == 1 ? g_kh : g_vh);
    __nv_bfloat16* ol = (o == 0) ? g_ql : (o == 1 ? g_kl : g_vl);
    const size_t r0 = (size_t)(m0 + wid * 16 + (lane >> 2)) * H_DIM;
    const size_t r1 = r0 + 8 * H_DIM;
#pragma unroll
    for (int j = 0; j < 16; j++) {
        int col = j * 8 + (lane & 3) * 2;
        uint32_t h, l;
        split2(c[j][0] * sc, c[j][1] * sc, h, l);
        *(uint32_t*)&oh[r0 + col] = h;
        *(uint32_t*)&ol[r0 + col] = l;
        split2(c[j][2] * sc, c[j][3] * sc, h, l);
        *(uint32_t*)&oh[r1 + col] = h;
        *(uint32_t*)&ol[r1 + col] = l;
    }
}

// ---------------------------------------------------------------------------
// Kernel 2: causal flash attention.  QT=128, KT=64, block=256 (8 warps).
// grid=(24,8):  bx<16 -> split-KV pair for qt=15-(bx>>1), half h=bx&1;
//               bx>=16 -> single CTA for qt=23-bx (7..0).
// smem (bf16 elems): Qh 0, Ql 17408; KV stage s @ 34816+s*34816:
//   Kh +0, Kl +8704, Vh +17408, Vl +26112.  Total 208896 B -> 1 CTA/SM, 8 warps.
// ---------------------------------------------------------------------------
#define AST 136
#define KVSTG_E 34816
#define ATT_SMEM 208896

__global__ __launch_bounds__(256, 1)
void attn_mma_kernel(float* __restrict__ out)
{
    extern __shared__ __align__(16) __nv_bfloat16 sm_a[];

    const int tid  = threadIdx.x;
    const int lane = tid & 31;
    const int wid  = tid >> 5;
    const int b    = blockIdx.y;
    const int bx   = blockIdx.x;

    int qt, h, sbeg, send;
    bool split_kv;
    if (bx < 16) {
        split_kv = true;
        qt   = 15 - (bx >> 1);
        h    = bx & 1;
        sbeg = h * (qt + 1);
        send = sbeg + qt + 1;
    } else {
        split_kv = false;
        qt   = 23 - bx;
        h    = 0;
        sbeg = 0;
        send = 2 * qt + 2;
    }
    const int q0 = qt * 128;

    const uint32_t qh_base = smem_u32(sm_a);

    auto issue_kv = [&](int kts, int s) {
        uint32_t kb = smem_u32(sm_a + 34816 + s * KVSTG_E);
#pragma unroll
        for (int i = 0; i < 4; i++) {
            int idx = tid + i * 256;           // 0..1023: 64 rows x 16 chunks
            int row = idx >> 4, c8 = idx & 15;
            size_t g = ((size_t)b * S_LEN + kts * 64 + row) * H_DIM + c8 * 8;
            uint32_t d = kb + (row * AST + c8 * 8) * 2;
            cp16(d,         &g_kh[g]);
            cp16(d + 17408, &g_kl[g]);
            cp16(d + 34816, &g_vh[g]);
            cp16(d + 52224, &g_vl[g]);
        }
    };

    issue_kv(sbeg, sbeg & 1); CP_COMMIT();

    // --- stage Q (hi/lo), 128 rows, persists across kv steps ---
#pragma unroll
    for (int i = 0; i < 8; i++) {
        int idx = tid + i * 256;               // 0..2047
        int row = idx >> 4, c8 = idx & 15;
        size_t g = ((size_t)b * S_LEN + q0 + row) * H_DIM + c8 * 8;
        *(uint4*)&sm_a[row * AST + c8 * 8]         = *(const uint4*)&g_qh[g];
        *(uint4*)&sm_a[17408 + row * AST + c8 * 8] = *(const uint4*)&g_ql[g];
    }

    float o_[16][4];
#pragma unroll
    for (int d = 0; d < 16; d++)
#pragma unroll
        for (int i = 0; i < 4; i++) o_[d][i] = 0.f;
    float lsum0 = 0.f, lsum1 = 0.f;

    const int colb = (lane & 3) * 2;
    const int r0l  = wid * 16 + (lane >> 2);
    const int r1l  = r0l + 8;
    const int kbrow = ((lane >> 4) & 1) * 8 + (lane & 7);
    const int kbcol = ((lane >> 3) & 1) * 8;
    const int vbrow = ((lane >> 3) & 1) * 8 + (lane & 7);
    const int vbcol = ((lane >> 4) & 1) * 8;

    for (int kts = sbeg; kts < send; kts++) {
        if (kts + 1 < send) { issue_kv(kts + 1, (kts + 1) & 1); CP_COMMIT(); CP_WAIT1(); }
        else CP_WAIT0();
        __syncthreads();

        const uint32_t kb = smem_u32(sm_a + 34816 + (kts & 1) * KVSTG_E);
        const uint32_t vb = kb + 34816;        // Vh bytes

        // --- S = Q K^T  (this warp: 16 q x 64 k) ---
        float s[8][4];
#pragma unroll
        for (int j = 0; j < 8; j++)
#pragma unroll
            for (int i = 0; i < 4; i++) s[j][i] = 0.f;

#pragma unroll
        for (int kd = 0; kd < 8; kd++) {
            uint32_t ah[4], al[4];
            uint32_t aaddr = qh_base +
                ((wid * 16 + (lane & 15)) * AST + kd * 16 + ((lane >> 4) << 3)) * 2;
            ldmx4(ah, aaddr);
            ldmx4(al, aaddr + 34816);
#pragma unroll
            for (int jp = 0; jp < 4; jp++) {
                uint32_t bh[4], bl[4];
                uint32_t baddr = kb + ((jp * 16 + kbrow) * AST + kd * 16 + kbcol) * 2;
                ldmx4(bh, baddr);
                ldmx4(bl, baddr + 17408);
                mma16816(s[2 * jp],     ah[0], ah[1], ah[2], ah[3], bh[0], bh[1]);
                mma16816(s[2 * jp],     ah[0], ah[1], ah[2], ah[3], bl[0], bl[1]);
                mma16816(s[2 * jp],     al[0], al[1], al[2], al[3], bh[0], bh[1]);
                mma16816(s[2 * jp + 1], ah[0], ah[1], ah[2], ah[3], bh[2], bh[3]);
                mma16816(s[2 * jp + 1], ah[0], ah[1], ah[2], ah[3], bl[2], bl[3]);
                mma16816(s[2 * jp + 1], al[0], al[1], al[2], al[3], bh[2], bh[3]);
            }
        }

        // --- exp (+ causal mask), row sums ---
        const bool diag = (kts >= 2 * qt);
        const int dof = kts * 64 - q0;
        float rs0 = 0.f, rs1 = 0.f;
#pragma unroll
        for (int j = 0; j < 8; j++) {
            float e0 = __expf(s[j][0]);
            float e1 = __expf(s[j][1]);
            float e2 = __expf(s[j][2]);
            float e3 = __expf(s[j][3]);
            if (diag) {
                int cc = j * 8 + colb + dof;
                if (cc     > r0l) e0 = 0.f;
                if (cc + 1 > r0l) e1 = 0.f;
                if (cc     > r1l) e2 = 0.f;
                if (cc + 1 > r1l) e3 = 0.f;
            }
            s[j][0] = e0; s[j][1] = e1; s[j][2] = e2; s[j][3] = e3;
            rs0 += e0 + e1;
            rs1 += e2 + e3;
        }
        rs0 += __shfl_xor_sync(0xffffffffu, rs0, 1);
        rs0 += __shfl_xor_sync(0xffffffffu, rs0, 2);
        rs1 += __shfl_xor_sync(0xffffffffu, rs1, 1);
        rs1 += __shfl_xor_sync(0xffffffffu, rs1, 2);
        lsum0 += rs0;
        lsum1 += rs1;

        // --- O += P V (P A-frags in-register from S C-frags) ---
#pragma unroll
        for (int j2 = 0; j2 < 4; j2++) {
            uint32_t ph[4], pl[4];
            split2(s[2 * j2][0],     s[2 * j2][1],     ph[0], pl[0]);
            split2(s[2 * j2][2],     s[2 * j2][3],     ph[1], pl[1]);
            split2(s[2 * j2 + 1][0], s[2 * j2 + 1][1], ph[2], pl[2]);
            split2(s[2 * j2 + 1][2], s[2 * j2 + 1][3], ph[3], pl[3]);
#pragma unroll
            for (int d2 = 0; d2 < 8; d2++) {
                uint32_t vh[4], vl[4];
                uint32_t vaddr = vb + ((j2 * 16 + vbrow) * AST + d2 * 16 + vbcol) * 2;
                ldmx4t(vh, vaddr);
                ldmx4t(vl, vaddr + 17408);
                mma16816(o_[2 * d2],     ph[0], ph[1], ph[2], ph[3], vh[0], vh[1]);
                mma16816(o_[2 * d2],     ph[0], ph[1], ph[2], ph[3], vl[0], vl[1]);
                mma16816(o_[2 * d2],     pl[0], pl[1], pl[2], pl[3], vh[0], vh[1]);
                mma16816(o_[2 * d2 + 1], ph[0], ph[1], ph[2], ph[3], vh[2], vh[3]);
                mma16816(o_[2 * d2 + 1], ph[0], ph[1], ph[2], ph[3], vl[2], vl[3]);
                mma16816(o_[2 * d2 + 1], pl[0], pl[1], pl[2], pl[3], vh[2], vh[3]);
            }
        }
        __syncthreads();
    }

    // --- epilogue ---
    if (!split_kv) {
        const float inv0 = 1.f / lsum0;
        const float inv1 = 1.f / lsum1;
        const size_t gr0 = ((size_t)b * S_LEN + q0 + r0l) * H_DIM;
        const size_t gr1 = gr0 + 8 * H_DIM;
#pragma unroll
        for (int dn = 0; dn < 16; dn++) {
            int col = dn * 8 + colb;
            *(float2*)&out[gr0 + col] = make_float2(o_[dn][0] * inv0, o_[dn][1] * inv0);
            *(float2*)&out[gr1 + col] = make_float2(o_[dn][2] * inv1, o_[dn][3] * inv1);
        }
    } else {
        const size_t pbase = (size_t)(h * 8 + b) * 1024 + (q0 - 1024);
        float* p0 = &g_po[(pbase + r0l) * 128];
        float* p1 = &g_po[(pbase + r1l) * 128];
#pragma unroll
        for (int dn = 0; dn < 16; dn++) {
            int col = dn * 8 + colb;
            *(float2*)&p0[col] = make_float2(o_[dn][0], o_[dn][1]);
            *(float2*)&p1[col] = make_float2(o_[dn][2], o_[dn][3]);
        }
        if ((lane & 3) == 0) {
            g_pl[pbase + r0l] = lsum0;
            g_pl[pbase + r1l] = lsum1;
        }
    }
}

// ---------------------------------------------------------------------------
// Kernel 3: combine split-KV partials (rows 1024..2047 of each batch)
// ---------------------------------------------------------------------------
__global__ __launch_bounds__(256)
void combine_kernel(float* __restrict__ out)
{
    int idx = blockIdx.x * 256 + threadIdx.x;      // float4 units, 262144 total
    int row = idx >> 5;                             // 0..8191
    int d4  = (idx & 31) * 4;
    int b   = row >> 10;
    int r   = row & 1023;
    float l = g_pl[(size_t)b * 1024 + r] + g_pl[(size_t)(8 + b) * 1024 + r];
    float inv = 1.f / l;
    size_t i0 = ((size_t)b * 1024 + r) * 128 + d4;
    size_t i1 = ((size_t)(8 + b) * 1024 + r) * 128 + d4;
    float4 a = *(const float4*)&g_po[i0];
    float4 c = *(const float4*)&g_po[i1];
    float4 o;
    o.x = (a.x + c.x) * inv;
    o.y = (a.y + c.y) * inv;
    o.z = (a.z + c.z) * inv;
    o.w = (a.w + c.w) * inv;
    *(float4*)&out[((size_t)b * S_LEN + 1024 + r) * H_DIM + d4] = o;
}

// ---------------------------------------------------------------------------
extern "C" void kernel_launch(void* const* d_in, const int* in_sizes, int n_in,
                              void* d_out, int out_size)
{
    const float* X    = (const float*)d_in[0];
    const float* mask = (const float*)d_in[1];
    const float* Wq   = (const float*)d_in[2];
    const float* Wk   = (const float*)d_in[3];
    const float* Wv   = (const float*)d_in[4];
    float* out        = (float*)d_out;

    split_x_kernel<<<M_TOTAL * E_DIM / 4 / 256, 256>>>(X, mask);
    split_w_kernel<<<3 * H_DIM * E_DIM / 4 / 256, 256>>>(Wq, Wk, Wv);

    cudaFuncSetAttribute(qkv_mma_kernel,
                         cudaFuncAttributeMaxDynamicSharedMemorySize, QKV_SMEM);
    dim3 g1(M_TOTAL / 64, 3);
    qkv_mma_kernel<<<g1, 128, QKV_SMEM>>>();

    cudaFuncSetAttribute(attn_mma_kernel,
                         cudaFuncAttributeMaxDynamicSharedMemorySize, ATT_SMEM);
    dim3 g2(24, B_SZ);
    attn_mma_kernel<<<g2, 256, ATT_SMEM>>>(out);

    combine_kernel<<<1024, 256>>>(out);
}